// round 4
// baseline (speedup 1.0000x reference)
#include <cuda_runtime.h>
#include <cuda_bf16.h>

// RiskAwareMAE single-kernel streaming reduction.
// Key change R4: __launch_bounds__(256, 4) -> 64-reg ceiling so the 8 LDG.128
// of the 4-way batch stay live (MLP_p1 ~ 8) instead of serializing at 32 regs.

#define NBLOCKS 1216
#define NTHREADS 256
#define NWARPS (NTHREADS / 32)

__device__ float g_partials[NBLOCKS];
__device__ unsigned int g_ticket = 0;   // wraps to 0 via atomicInc modulo

__device__ __forceinline__ float warp_reduce(float v) {
#pragma unroll
    for (int off = 16; off > 0; off >>= 1)
        v += __shfl_xor_sync(0xFFFFFFFFu, v, off);
    return v;
}

__device__ __forceinline__ float loss_elem(float o, float t,
                                           float p0, float inv_step,
                                           float invP, float Pm1) {
    float j = rintf((t - p0) * inv_step);
    j = fminf(fmaxf(j, 0.0f), Pm1);
    float factor = (j + 1.0f) * invP;
    float e = t - o;
    return fmaxf((factor - 1.0f) * e, factor * e);
}

__global__ void __launch_bounds__(NTHREADS, 4)
risk_mae_fused(const float4* __restrict__ out4,
               const float4* __restrict__ tgt4,
               const float* __restrict__ perc,
               float* __restrict__ d_out,
               int n4, int P, float inv_n) {
    const float p0 = __ldg(&perc[0]);
    const float pl = __ldg(&perc[P - 1]);
    const float Pm1 = (float)(P - 1);
    const float inv_step = Pm1 / (pl - p0);
    const float invP = 1.0f / (float)P;

    const int stride = gridDim.x * blockDim.x;
    int i = blockIdx.x * blockDim.x + threadIdx.x;

    float acc = 0.0f;

    // 4-way batch: 8 independent LDG.128 issued before any consumption.
    for (; i + 3 * stride < n4; i += 4 * stride) {
        float4 o0 = out4[i];
        float4 t0 = tgt4[i];
        float4 o1 = out4[i + stride];
        float4 t1 = tgt4[i + stride];
        float4 o2 = out4[i + 2 * stride];
        float4 t2 = tgt4[i + 2 * stride];
        float4 o3 = out4[i + 3 * stride];
        float4 t3 = tgt4[i + 3 * stride];
        float a0 = 0.f, a1 = 0.f, a2 = 0.f, a3 = 0.f;
        a0 += loss_elem(o0.x, t0.x, p0, inv_step, invP, Pm1);
        a0 += loss_elem(o0.y, t0.y, p0, inv_step, invP, Pm1);
        a0 += loss_elem(o0.z, t0.z, p0, inv_step, invP, Pm1);
        a0 += loss_elem(o0.w, t0.w, p0, inv_step, invP, Pm1);
        a1 += loss_elem(o1.x, t1.x, p0, inv_step, invP, Pm1);
        a1 += loss_elem(o1.y, t1.y, p0, inv_step, invP, Pm1);
        a1 += loss_elem(o1.z, t1.z, p0, inv_step, invP, Pm1);
        a1 += loss_elem(o1.w, t1.w, p0, inv_step, invP, Pm1);
        a2 += loss_elem(o2.x, t2.x, p0, inv_step, invP, Pm1);
        a2 += loss_elem(o2.y, t2.y, p0, inv_step, invP, Pm1);
        a2 += loss_elem(o2.z, t2.z, p0, inv_step, invP, Pm1);
        a2 += loss_elem(o2.w, t2.w, p0, inv_step, invP, Pm1);
        a3 += loss_elem(o3.x, t3.x, p0, inv_step, invP, Pm1);
        a3 += loss_elem(o3.y, t3.y, p0, inv_step, invP, Pm1);
        a3 += loss_elem(o3.z, t3.z, p0, inv_step, invP, Pm1);
        a3 += loss_elem(o3.w, t3.w, p0, inv_step, invP, Pm1);
        acc += (a0 + a1) + (a2 + a3);
    }
    for (; i < n4; i += stride) {
        float4 o = out4[i];
        float4 t = tgt4[i];
        acc += loss_elem(o.x, t.x, p0, inv_step, invP, Pm1);
        acc += loss_elem(o.y, t.y, p0, inv_step, invP, Pm1);
        acc += loss_elem(o.z, t.z, p0, inv_step, invP, Pm1);
        acc += loss_elem(o.w, t.w, p0, inv_step, invP, Pm1);
    }

    // block reduction
    __shared__ float smem[NWARPS];
    acc = warp_reduce(acc);
    int wid = threadIdx.x >> 5;
    int lid = threadIdx.x & 31;
    if (lid == 0) smem[wid] = acc;
    __syncthreads();
    if (wid == 0) {
        float v = (lid < NWARPS) ? smem[lid] : 0.0f;
        v = warp_reduce(v);
        if (lid == 0) g_partials[blockIdx.x] = v;
    }

    // last-block final reduction (threadfence reduction pattern)
    __shared__ bool s_last;
    __threadfence();
    if (threadIdx.x == 0) {
        unsigned int ticket = atomicInc(&g_ticket, NBLOCKS - 1);
        s_last = (ticket == NBLOCKS - 1);
    }
    __syncthreads();
    if (s_last) {
        double dacc = 0.0;
        for (int k = threadIdx.x; k < NBLOCKS; k += NTHREADS)
            dacc = dacc + (double)g_partials[k];
#pragma unroll
        for (int off = 16; off > 0; off >>= 1)
            dacc += __shfl_xor_sync(0xFFFFFFFFu, dacc, off);
        __shared__ double dsm[NWARPS];
        if (lid == 0) dsm[wid] = dacc;
        __syncthreads();
        if (wid == 0) {
            double v = (lid < NWARPS) ? dsm[lid] : 0.0;
#pragma unroll
            for (int off = 16; off > 0; off >>= 1)
                v += __shfl_xor_sync(0xFFFFFFFFu, v, off);
            if (lid == 0) d_out[0] = (float)(v * (double)inv_n);
        }
    }
}

extern "C" void kernel_launch(void* const* d_in, const int* in_sizes, int n_in,
                              void* d_out, int out_size) {
    const float* outputs = (const float*)d_in[0];
    const float* targets = (const float*)d_in[1];
    const float* percentiles = (const float*)d_in[2];
    const int n = in_sizes[0];
    const int P = in_sizes[2];
    const int n4 = n / 4;

    risk_mae_fused<<<NBLOCKS, NTHREADS>>>(
        (const float4*)outputs, (const float4*)targets, percentiles,
        (float*)d_out, n4, P, 1.0f / (float)n);
}